// round 13
// baseline (speedup 1.0000x reference)
#include <cuda_runtime.h>

#define BB 16
#define SS 4096
#define HH 768
#define NSL 64                  // slices per batch
#define LL 64                   // rows (positions) per slice
#define NEGV (-1e30f)

// ---------------- scratch (static device globals; no allocation) ----------------
__device__ float g_part[BB * NSL * 9];    // per-slice 3x3 semiring partial products
__device__ float g_nump[BB * NSL];        // numerator partial sums (steps t>=1)
__device__ int   g_mskp[BB * NSL];        // mask partial sums (steps t>=1)
__device__ float g_em0[BB * 3];           // emissions row 0 per batch
__device__ float g_llh[BB];               // per-batch log-likelihood
__device__ unsigned int g_cnt[BB];        // per-batch arrival counters (monotonic, mod 64)
__device__ unsigned int g_bcnt;           // batch-finalize counter (monotonic, mod 16)

__device__ __forceinline__ float lse3(float a, float b, float c) {
    float m = fmaxf(a, fmaxf(b, c));
    return m + __logf(__expf(a - m) + __expf(b - m) + __expf(c - m));
}

// ---------------- single fused kernel: emissions + scan + finalize ----------------
// grid = BB*NSL = 1024 blocks of 256. Block (b,slice) owns rows [slice*64, +64).
// Phase 1: warp w computes emissions for rows w*8..w*8+7 (8-deep load MLP),
//          butterfly-reduces, lanes 0..7 write the 8 rows to smem.
// Phase 2: warps 0 and 1 each scan 32 steps via a 5-level shuffle tree (the
//          cheapest MUFU formulation: 45 lse3 instr per warp); 9-thread combine.
// Phase 3: LAST block per batch (monotonic counter, mod-64) reduces the 64 slice
//          partials entry-parallel; 16th batch-finalizer writes out[0].
__global__ void __launch_bounds__(256) fused_kernel(const float* __restrict__ x,
                                                    const float* __restrict__ W,
                                                    const float* __restrict__ bias,
                                                    const int*   __restrict__ y,
                                                    const int*   __restrict__ mask,
                                                    const float* __restrict__ trans,
                                                    const float* __restrict__ start_t,
                                                    const float* __restrict__ end_t,
                                                    float* __restrict__ out) {
    __shared__ float s_em[LL][5];          // stride 5 -> conflict-free column reads
    __shared__ float wP[2 * 9];
    __shared__ float wN[2];
    __shared__ int   wK[2];
    __shared__ float sM[NSL * 9];
    __shared__ float sN[NSL];
    __shared__ int   sK[NSL];
    __shared__ int   s_flag;

    int b     = blockIdx.x >> 6;
    int slice = blockIdx.x & (NSL - 1);
    int tid   = threadIdx.x;
    int wid   = tid >> 5;
    int lane  = tid & 31;
    int R     = b * SS + slice * LL;        // global row base for this block

    // ---- phase 1: emissions. warp wid computes rows R + wid*8 .. +7 ----
    {
        int row0 = R + wid * 8;
        const float4* x4 = reinterpret_cast<const float4*>(x);
        const float4* w4 = reinterpret_cast<const float4*>(W);

        float a0[8], a1[8], a2[8];
#pragma unroll
        for (int r = 0; r < 8; r++) { a0[r] = 0.f; a1[r] = 0.f; a2[r] = 0.f; }

#pragma unroll
        for (int j = 0; j < 6; j++) {
            int idx = lane + 32 * j;          // 0..191
            float4 w0 = __ldg(w4 + idx);
            float4 w1 = __ldg(w4 + 192 + idx);
            float4 w2 = __ldg(w4 + 384 + idx);
#pragma unroll
            for (int r = 0; r < 8; r++) {
                float4 xv = __ldg(x4 + (size_t)(row0 + r) * (HH / 4) + idx);
                a0[r] = fmaf(xv.x, w0.x, fmaf(xv.y, w0.y, fmaf(xv.z, w0.z, fmaf(xv.w, w0.w, a0[r]))));
                a1[r] = fmaf(xv.x, w1.x, fmaf(xv.y, w1.y, fmaf(xv.z, w1.z, fmaf(xv.w, w1.w, a1[r]))));
                a2[r] = fmaf(xv.x, w2.x, fmaf(xv.y, w2.y, fmaf(xv.z, w2.z, fmaf(xv.w, w2.w, a2[r]))));
            }
        }
#pragma unroll
        for (int off = 16; off; off >>= 1) {
#pragma unroll
            for (int r = 0; r < 8; r++) {
                a0[r] += __shfl_xor_sync(0xFFFFFFFFu, a0[r], off);
                a1[r] += __shfl_xor_sync(0xFFFFFFFFu, a1[r], off);
                a2[r] += __shfl_xor_sync(0xFFFFFFFFu, a2[r], off);
            }
        }
        float b0 = __ldg(bias + 0), b1 = __ldg(bias + 1), b2 = __ldg(bias + 2);
#pragma unroll
        for (int r = 0; r < 8; r++) {
            if (lane == r) {                   // compile-time r -> no reg spill
                int lr = wid * 8 + r;
                s_em[lr][0] = a0[r] + b0;
                s_em[lr][1] = a1[r] + b1;
                s_em[lr][2] = a2[r] + b2;
            }
        }
    }
    __syncthreads();

    // ---- phase 2: warps 0,1 scan 32 steps each via shuffle tree ----
    if (wid < 2) {
        int lr    = wid * 32 + lane;       // local row 0..63
        int s_idx = slice * LL + lr;       // position within sequence
        int t     = R + lr;                // flat index

        float tr[9];
#pragma unroll
        for (int i = 0; i < 9; i++) tr[i] = __ldg(trans + i);

        float P[9];
        float nsum = 0.f;
        int   msum = 0;

        int mk = mask[t];
        if (s_idx > 0 && mk) {
            float e0 = s_em[lr][0], e1 = s_em[lr][1], e2 = s_em[lr][2];
#pragma unroll
            for (int i = 0; i < 3; i++) {
                P[i * 3 + 0] = tr[i * 3 + 0] + e0;
                P[i * 3 + 1] = tr[i * 3 + 1] + e1;
                P[i * 3 + 2] = tr[i * 3 + 2] + e2;
            }
            int yt = y[t], yp = y[t - 1];
            float ey = (yt == 0) ? e0 : ((yt == 1) ? e1 : e2);
            nsum = tr[yp * 3 + yt] + ey;
            msum = 1;
        } else {
#pragma unroll
            for (int i = 0; i < 9; i++) P[i] = NEGV;
            P[0] = 0.f; P[4] = 0.f; P[8] = 0.f;
        }

        if (s_idx == 0 && lane == 0) {     // block (b,0), warp 0 only
            g_em0[b * 3 + 0] = s_em[0][0];
            g_em0[b * 3 + 1] = s_em[0][1];
            g_em0[b * 3 + 2] = s_em[0][2];
        }

        // order-preserving suffix tree: lane 0 ends with the 32-step product
#pragma unroll
        for (int st = 1; st < 32; st <<= 1) {
            float Q[9];
#pragma unroll
            for (int i = 0; i < 9; i++) Q[i] = __shfl_down_sync(0xFFFFFFFFu, P[i], st);
            float nq = __shfl_down_sync(0xFFFFFFFFu, nsum, st);
            int   mq = __shfl_down_sync(0xFFFFFFFFu, msum, st);
            float C[9];
#pragma unroll
            for (int i = 0; i < 3; i++) {
#pragma unroll
                for (int j = 0; j < 3; j++) {
                    C[i * 3 + j] = lse3(P[i * 3 + 0] + Q[0 * 3 + j],
                                        P[i * 3 + 1] + Q[1 * 3 + j],
                                        P[i * 3 + 2] + Q[2 * 3 + j]);
                }
            }
#pragma unroll
            for (int i = 0; i < 9; i++) P[i] = C[i];
            nsum += nq;
            msum += mq;
        }

        if (lane == 0) {
#pragma unroll
            for (int i = 0; i < 9; i++) wP[wid * 9 + i] = P[i];
            wN[wid] = nsum;
            wK[wid] = msum;
        }
    }
    __syncthreads();

    // ---- combine the 2 warp partials (warp 0, lanes 0..8) + publish ----
    if (wid == 0) {
        float cv = 0.f;
        if (lane < 9) {
            int i = lane / 3, c = lane - i * 3;
            cv = lse3(wP[i * 3 + 0] + wP[9 + 0 + c],
                      wP[i * 3 + 1] + wP[9 + 3 + c],
                      wP[i * 3 + 2] + wP[9 + 6 + c]);
        }
        __syncwarp();
        if (lane < 9) wP[lane] = cv;
        if (lane == 0) { wN[0] += wN[1]; wK[0] += wK[1]; }
        __syncwarp();
        if (lane == 0) {
            int pi = b * NSL + slice;
#pragma unroll
            for (int i = 0; i < 9; i++) g_part[pi * 9 + i] = wP[i];
            g_nump[pi] = wN[0];
            g_mskp[pi] = wK[0];
            __threadfence();
            unsigned int old = atomicAdd(&g_cnt[b], 1u);
            s_flag = ((old & (NSL - 1u)) == NSL - 1u) ? 1 : 0;  // mod 64 (graph replays)
        }
    }
    __syncthreads();
    if (!s_flag) return;

    // ---- phase 3: last block of batch b finalizes ----
    for (int i = tid; i < NSL * 9; i += 256) sM[i] = __ldcg(&g_part[b * NSL * 9 + i]);
    if (tid < NSL) {
        sN[tid] = __ldcg(&g_nump[b * NSL + tid]);
        sK[tid] = __ldcg(&g_mskp[b * NSL + tid]);
    }
    __syncthreads();

    // entry-parallel tree: depth 6, one lse3 per thread-job per level
    for (int st = 1; st < NSL; st <<= 1) {
        int pairs = NSL / (2 * st);
        int jobs  = pairs * 9;
        float Cv[2]; int off[2]; int cnt = 0;
        for (int j = tid; j < jobs; j += 256) {
            int p = j / 9, e = j - p * 9;
            int i = e / 3, c = e - i * 3;
            int m = p * 2 * st;
            const float* A  = &sM[m * 9];
            const float* Bm = &sM[(m + st) * 9];
            Cv[cnt]  = lse3(A[i * 3 + 0] + Bm[0 + c],
                            A[i * 3 + 1] + Bm[3 + c],
                            A[i * 3 + 2] + Bm[6 + c]);
            off[cnt] = m * 9 + e;
            cnt++;
        }
        bool dos = tid < pairs;
        float nv = 0.f; int kv = 0;
        if (dos) { int m = tid * 2 * st; nv = sN[m] + sN[m + st]; kv = sK[m] + sK[m + st]; }
        __syncthreads();
        for (int q = 0; q < cnt; q++) sM[off[q]] = Cv[q];
        if (dos) { int m = tid * 2 * st; sN[m] = nv; sK[m] = kv; }
        __syncthreads();
    }

    if (tid == 0) {
        int bS = b * SS;
        float e0 = __ldcg(&g_em0[b * 3 + 0]);
        float e1 = __ldcg(&g_em0[b * 3 + 1]);
        float e2 = __ldcg(&g_em0[b * 3 + 2]);
        float p0 = start_t[0] + e0;
        float p1 = start_t[1] + e1;
        float p2 = start_t[2] + e2;

        float af0 = lse3(p0 + sM[0], p1 + sM[3], p2 + sM[6]);
        float af1 = lse3(p0 + sM[1], p1 + sM[4], p2 + sM[7]);
        float af2 = lse3(p0 + sM[2], p1 + sM[5], p2 + sM[8]);
        float denom = lse3(af0 + end_t[0], af1 + end_t[1], af2 + end_t[2]);

        int y0 = y[bS];
        float em0y = (y0 == 0) ? e0 : ((y0 == 1) ? e1 : e2);
        float num  = start_t[y0] + em0y + sN[0];
        int   slen = mask[bS] + sK[0];
        num += end_t[y[bS + slen - 1]];

        g_llh[b] = num - denom;
        __threadfence();
        unsigned int ob = atomicAdd(&g_bcnt, 1u);
        if ((ob & (BB - 1u)) == BB - 1u) {                 // 16th batch-finalizer
            float s = 0.f;
#pragma unroll
            for (int i = 0; i < BB; i++) s += __ldcg(&g_llh[i]);
            out[0] = -s / (float)BB;
        }
    }
}

// ---------------- launch ----------------------------------------------------------
extern "C" void kernel_launch(void* const* d_in, const int* in_sizes, int n_in,
                              void* d_out, int out_size) {
    const float* x     = (const float*)d_in[0];
    const int*   y     = (const int*)  d_in[1];
    const int*   mask  = (const int*)  d_in[2];
    const float* W     = (const float*)d_in[3];
    const float* bias  = (const float*)d_in[4];
    const float* st    = (const float*)d_in[5];
    const float* en    = (const float*)d_in[6];
    const float* trans = (const float*)d_in[7];
    float* out = (float*)d_out;

    fused_kernel<<<BB * NSL, 256>>>(x, W, bias, y, mask, trans, st, en, out);
}

// round 15
// speedup vs baseline: 1.1326x; 1.1326x over previous
#include <cuda_runtime.h>

#define BB 16
#define SS 4096
#define HH 768
#define RPW 8                   // rows per warp in emis kernel
#define NCHK 16                 // chunks per batch in scan kernel
#define RPC 256                 // rows per chunk (8 warps x 32)
#define NEGV (-1e30f)

// ---------------- scratch (static device globals; no allocation) ----------------
__device__ float g_em[BB * SS * 3];       // emissions, 786 KB
__device__ float g_part[BB * NCHK * 9];   // per-chunk 3x3 semiring partial products
__device__ float g_nump[BB * NCHK];       // numerator partials
__device__ int   g_mskp[BB * NCHK];       // mask partials
__device__ float g_llh[BB];               // per-batch llh
__device__ unsigned int g_cnt[BB];        // per-batch arrival counters (monotonic, mod 16)
__device__ unsigned int g_bcnt;           // finalize counter (monotonic, mod 16)

__device__ __forceinline__ float lse3(float a, float b, float c) {
    float m = fmaxf(a, fmaxf(b, c));
    return m + __logf(__expf(a - m) + __expf(b - m) + __expf(c - m));
}

// ---------------- kernel 1: emissions = x @ W^T + b (R3 config: 8 rows/warp) -----
// Barrier-free streamer: measured 40.4us / DRAM 62% standalone.
__global__ void __launch_bounds__(256) emis_kernel(const float* __restrict__ x,
                                                   const float* __restrict__ W,
                                                   const float* __restrict__ bias) {
    int gw   = (blockIdx.x * 256 + threadIdx.x) >> 5;   // warp index
    int lane = threadIdx.x & 31;
    int row0 = gw * RPW;
    if (row0 >= BB * SS) return;

    const float4* x4 = reinterpret_cast<const float4*>(x);
    const float4* w4 = reinterpret_cast<const float4*>(W);

    float a0[RPW], a1[RPW], a2[RPW];
#pragma unroll
    for (int r = 0; r < RPW; r++) { a0[r] = 0.f; a1[r] = 0.f; a2[r] = 0.f; }

#pragma unroll
    for (int j = 0; j < 6; j++) {
        int idx = lane + 32 * j;                  // 0..191
        float4 w0 = __ldg(w4 + idx);
        float4 w1 = __ldg(w4 + 192 + idx);
        float4 w2 = __ldg(w4 + 384 + idx);
#pragma unroll
        for (int r = 0; r < RPW; r++) {
            float4 xv = __ldg(x4 + (size_t)(row0 + r) * (HH / 4) + idx);
            a0[r] = fmaf(xv.x, w0.x, fmaf(xv.y, w0.y, fmaf(xv.z, w0.z, fmaf(xv.w, w0.w, a0[r]))));
            a1[r] = fmaf(xv.x, w1.x, fmaf(xv.y, w1.y, fmaf(xv.z, w1.z, fmaf(xv.w, w1.w, a1[r]))));
            a2[r] = fmaf(xv.x, w2.x, fmaf(xv.y, w2.y, fmaf(xv.z, w2.z, fmaf(xv.w, w2.w, a2[r]))));
        }
    }
#pragma unroll
    for (int off = 16; off; off >>= 1) {
#pragma unroll
        for (int r = 0; r < RPW; r++) {
            a0[r] += __shfl_xor_sync(0xFFFFFFFFu, a0[r], off);
            a1[r] += __shfl_xor_sync(0xFFFFFFFFu, a1[r], off);
            a2[r] += __shfl_xor_sync(0xFFFFFFFFu, a2[r], off);
        }
    }
    if (lane < RPW) {
        float b0 = __ldg(bias + 0), b1 = __ldg(bias + 1), b2 = __ldg(bias + 2);
        int row = row0 + lane;
        g_em[row * 3 + 0] = a0[lane] + b0;
        g_em[row * 3 + 1] = a1[lane] + b1;
        g_em[row * 3 + 2] = a2[lane] + b2;
    }
}

// ---------------- kernel 2: scan + finalize in one launch -------------------------
// grid = BB*NCHK = 256 blocks x 256. Block (b,chunk) owns rows [chunk*256, +256).
// Warp w scans its 32-step slice via the 5-level shuffle tree (cheapest MUFU form);
// depth-3 entry-parallel combine over 8 warp partials; last block per batch
// (monotonic counter, mod 16) reduces the 16 chunk partials and finalizes.
__global__ void __launch_bounds__(256) scan_kernel(const int*   __restrict__ y,
                                                   const int*   __restrict__ mask,
                                                   const float* __restrict__ trans,
                                                   const float* __restrict__ start_t,
                                                   const float* __restrict__ end_t,
                                                   float* __restrict__ out) {
    __shared__ float wP[8 * 9];
    __shared__ float wN[8];
    __shared__ int   wK[8];
    __shared__ float tM[NCHK * 9];
    __shared__ float tN[NCHK];
    __shared__ int   tK[NCHK];
    __shared__ int   s_flag;

    int b     = blockIdx.x >> 4;
    int chunk = blockIdx.x & (NCHK - 1);
    int tid   = threadIdx.x;
    int wid   = tid >> 5;
    int lane  = tid & 31;

    // ---- per-warp scan of 32 steps ----
    {
        int lr    = wid * 32 + lane;        // row in chunk, 0..255
        int s_idx = chunk * RPC + lr;       // position in sequence
        int t     = b * SS + s_idx;         // flat index

        float tr[9];
#pragma unroll
        for (int i = 0; i < 9; i++) tr[i] = __ldg(trans + i);

        float P[9];
        float nsum = 0.f;
        int   msum = 0;

        int mk = mask[t];
        if (s_idx > 0 && mk) {
            float e0 = g_em[t * 3 + 0], e1 = g_em[t * 3 + 1], e2 = g_em[t * 3 + 2];
#pragma unroll
            for (int i = 0; i < 3; i++) {
                P[i * 3 + 0] = tr[i * 3 + 0] + e0;
                P[i * 3 + 1] = tr[i * 3 + 1] + e1;
                P[i * 3 + 2] = tr[i * 3 + 2] + e2;
            }
            int yt = y[t], yp = y[t - 1];
            float ey = (yt == 0) ? e0 : ((yt == 1) ? e1 : e2);
            nsum = tr[yp * 3 + yt] + ey;
            msum = 1;
        } else {
#pragma unroll
            for (int i = 0; i < 9; i++) P[i] = NEGV;
            P[0] = 0.f; P[4] = 0.f; P[8] = 0.f;
        }

        // order-preserving suffix tree: lane 0 ends with the 32-step product
#pragma unroll
        for (int st = 1; st < 32; st <<= 1) {
            float Q[9];
#pragma unroll
            for (int i = 0; i < 9; i++) Q[i] = __shfl_down_sync(0xFFFFFFFFu, P[i], st);
            float nq = __shfl_down_sync(0xFFFFFFFFu, nsum, st);
            int   mq = __shfl_down_sync(0xFFFFFFFFu, msum, st);
            float C[9];
#pragma unroll
            for (int i = 0; i < 3; i++) {
#pragma unroll
                for (int j = 0; j < 3; j++) {
                    C[i * 3 + j] = lse3(P[i * 3 + 0] + Q[0 * 3 + j],
                                        P[i * 3 + 1] + Q[1 * 3 + j],
                                        P[i * 3 + 2] + Q[2 * 3 + j]);
                }
            }
#pragma unroll
            for (int i = 0; i < 9; i++) P[i] = C[i];
            nsum += nq;
            msum += mq;
        }

        if (lane == 0) {
#pragma unroll
            for (int i = 0; i < 9; i++) wP[wid * 9 + i] = P[i];
            wN[wid] = nsum;
            wK[wid] = msum;
        }
    }
    __syncthreads();

    // ---- depth-3 entry-parallel tree over the 8 warp partials ----
    for (int st = 1; st < 8; st <<= 1) {
        int pairs = 8 / (2 * st);
        int jobs  = pairs * 9;
        float cv = 0.f; int off = 0;
        bool doj = tid < jobs;
        if (doj) {
            int p = tid / 9, e = tid - p * 9;
            int i = e / 3, c = e - i * 3;
            int m = p * 2 * st;
            const float* A  = &wP[m * 9];
            const float* Bm = &wP[(m + st) * 9];
            cv  = lse3(A[i * 3 + 0] + Bm[0 + c],
                       A[i * 3 + 1] + Bm[3 + c],
                       A[i * 3 + 2] + Bm[6 + c]);
            off = m * 9 + e;
        }
        bool dos = tid < pairs;
        float nv = 0.f; int kv = 0;
        if (dos) { int m = tid * 2 * st; nv = wN[m] + wN[m + st]; kv = wK[m] + wK[m + st]; }
        __syncthreads();
        if (doj) wP[off] = cv;
        if (dos) { int m = tid * 2 * st; wN[m] = nv; wK[m] = kv; }
        __syncthreads();
    }

    // ---- publish chunk partial + arrival bump ----
    if (tid == 0) {
        int pi = b * NCHK + chunk;
#pragma unroll
        for (int i = 0; i < 9; i++) g_part[pi * 9 + i] = wP[i];
        g_nump[pi] = wN[0];
        g_mskp[pi] = wK[0];
        __threadfence();
        unsigned int old = atomicAdd(&g_cnt[b], 1u);
        s_flag = ((old & (NCHK - 1u)) == NCHK - 1u) ? 1 : 0;   // mod 16 (graph replays)
    }
    __syncthreads();
    if (!s_flag) return;

    // ---- last block of batch b: reduce 16 chunk partials + finalize ----
    if (tid < NCHK * 9) tM[tid] = __ldcg(&g_part[b * NCHK * 9 + tid]);
    if (tid < NCHK) {
        tN[tid] = __ldcg(&g_nump[b * NCHK + tid]);
        tK[tid] = __ldcg(&g_mskp[b * NCHK + tid]);
    }
    __syncthreads();

    for (int st = 1; st < NCHK; st <<= 1) {
        int pairs = NCHK / (2 * st);
        int jobs  = pairs * 9;
        float cv = 0.f; int off = 0;
        bool doj = tid < jobs;
        if (doj) {
            int p = tid / 9, e = tid - p * 9;
            int i = e / 3, c = e - i * 3;
            int m = p * 2 * st;
            const float* A  = &tM[m * 9];
            const float* Bm = &tM[(m + st) * 9];
            cv  = lse3(A[i * 3 + 0] + Bm[0 + c],
                       A[i * 3 + 1] + Bm[3 + c],
                       A[i * 3 + 2] + Bm[6 + c]);
            off = m * 9 + e;
        }
        bool dos = tid < pairs;
        float nv = 0.f; int kv = 0;
        if (dos) { int m = tid * 2 * st; nv = tN[m] + tN[m + st]; kv = tK[m] + tK[m + st]; }
        __syncthreads();
        if (doj) tM[off] = cv;
        if (dos) { int m = tid * 2 * st; tN[m] = nv; tK[m] = kv; }
        __syncthreads();
    }

    if (tid == 0) {
        int bS = b * SS;
        float e0 = g_em[bS * 3 + 0], e1 = g_em[bS * 3 + 1], e2 = g_em[bS * 3 + 2];
        float p0 = start_t[0] + e0;
        float p1 = start_t[1] + e1;
        float p2 = start_t[2] + e2;

        float af0 = lse3(p0 + tM[0], p1 + tM[3], p2 + tM[6]);
        float af1 = lse3(p0 + tM[1], p1 + tM[4], p2 + tM[7]);
        float af2 = lse3(p0 + tM[2], p1 + tM[5], p2 + tM[8]);
        float denom = lse3(af0 + end_t[0], af1 + end_t[1], af2 + end_t[2]);

        int y0 = y[bS];
        float em0y = (y0 == 0) ? e0 : ((y0 == 1) ? e1 : e2);
        float num  = start_t[y0] + em0y + tN[0];
        int   slen = mask[bS] + tK[0];
        num += end_t[y[bS + slen - 1]];

        g_llh[b] = num - denom;
        __threadfence();
        unsigned int ob = atomicAdd(&g_bcnt, 1u);
        if ((ob & (BB - 1u)) == BB - 1u) {                     // 16th finalizer
            float s = 0.f;
#pragma unroll
            for (int i = 0; i < BB; i++) s += __ldcg(&g_llh[i]);
            out[0] = -s / (float)BB;
        }
    }
}

// ---------------- launch ----------------------------------------------------------
extern "C" void kernel_launch(void* const* d_in, const int* in_sizes, int n_in,
                              void* d_out, int out_size) {
    const float* x     = (const float*)d_in[0];
    const int*   y     = (const int*)  d_in[1];
    const int*   mask  = (const int*)  d_in[2];
    const float* W     = (const float*)d_in[3];
    const float* bias  = (const float*)d_in[4];
    const float* st    = (const float*)d_in[5];
    const float* en    = (const float*)d_in[6];
    const float* trans = (const float*)d_in[7];
    float* out = (float*)d_out;

    emis_kernel<<<(BB * SS) / (8 * RPW), 256>>>(x, W, bias);
    scan_kernel<<<BB * NCHK, 256>>>(y, mask, trans, st, en, out);
}